// round 7
// baseline (speedup 1.0000x reference)
#include <cuda_runtime.h>
#include <math.h>

#define BN   256   // batch
#define TN   512   // timesteps
#define HN   512   // hidden
#define INP  256   // input dim
#define G4   2048  // 4*HN
#define KC   16    // K-chunk

// Persistent device scratch (no allocation allowed).
__device__ float g_h2[2][BN * HN];   // ping-pong hidden state
__device__ float g_c[BN * HN];       // cell state (in-place safe)
__device__ float g_xW[BN * G4];      // precomputed x0 @ W_w + W_b

__device__ __forceinline__ float sigm(float x) { return 1.0f / (1.0f + expf(-x)); }

// Packed fp32x2 FMA (Blackwell FFMA2): d.lo += a.lo*b.lo, d.hi += a.hi*b.hi
#define FFMA2(d, a, b) \
    asm("fma.rn.f32x2 %0, %1, %2, %0;" : "+l"(d) : "l"(a), "l"(b))

// ---------------------------------------------------------------------------
// One-time: g_xW = x0 @ W_w + W_b      (M=256, K=256, N=2048)
// grid (4, 32), 256 threads, 64x64 tile, 4x4 micro-tile. Runs once; plain fp32.
// ---------------------------------------------------------------------------
__global__ __launch_bounds__(256) void xw_gemm(const float* __restrict__ x0,
                                               const float* __restrict__ Ww,
                                               const float* __restrict__ Wb)
{
    __shared__ float As[KC][68];
    __shared__ float Bs[KC][68];

    const int tid = threadIdx.x;
    const int tx = tid & 15, ty = tid >> 4;
    const int m0 = blockIdx.x * 64;
    const int j0 = blockIdx.y * 64;

    const int am = tid >> 2, ak4 = (tid & 3) * 4;   // A loader: 64 rows x 16 k
    const int bk = tid >> 4, bh4 = (tid & 15) * 4;  // B loader: 16 k x 64 cols

    float acc[4][4] = {};

    float4 av = *(const float4*)&x0[(m0 + am) * INP + ak4];
    float4 bv = *(const float4*)&Ww[(size_t)bk * G4 + j0 + bh4];

    for (int kc = 0; kc < INP; kc += KC) {
        __syncthreads();
        As[ak4 + 0][am] = av.x; As[ak4 + 1][am] = av.y;
        As[ak4 + 2][am] = av.z; As[ak4 + 3][am] = av.w;
        *(float4*)&Bs[bk][bh4] = bv;
        __syncthreads();
        if (kc + KC < INP) {
            av = *(const float4*)&x0[(m0 + am) * INP + kc + KC + ak4];
            bv = *(const float4*)&Ww[(size_t)(kc + KC + bk) * G4 + j0 + bh4];
        }
#pragma unroll
        for (int kk = 0; kk < KC; kk++) {
            float4 a = *(float4*)&As[kk][ty * 4];
            float4 b = *(float4*)&Bs[kk][tx * 4];
            float ar[4] = {a.x, a.y, a.z, a.w};
            float br[4] = {b.x, b.y, b.z, b.w};
#pragma unroll
            for (int i = 0; i < 4; i++)
#pragma unroll
                for (int j = 0; j < 4; j++) acc[i][j] += ar[i] * br[j];
        }
    }

#pragma unroll
    for (int i = 0; i < 4; i++) {
        int row = ty * 4 + i;
#pragma unroll
        for (int j = 0; j < 4; j++) {
            int c = tx * 4 + j;
            g_xW[(size_t)(m0 + row) * G4 + j0 + c] = acc[i][j] + Wb[j0 + c];
        }
    }
}

// ---------------------------------------------------------------------------
// One fused timestep: gates = g_xW + h_cur @ U_w, LSTM gating, mask, output,
// next-step xcorr drift on h[:, 0:2] folded into the epilogue.
// grid (4, 32): blockIdx.x -> 64 batch rows; blockIdx.y -> 16 hidden cols,
// covering gate columns { q*512 + 16*ny + hh : q in 0..3 } (64 GEMM cols).
//
// GEMM mainloop uses packed fma.rn.f32x2 (FFMA2). A is stored DUPLICATED in
// smem (As2[k][2m] == As2[k][2m+1] == A[m][k]) so one broadcast LDS.64 yields
// the {a,a} packed operand with zero MOVs; B pairs come packed from LDS.128.
// Double-buffered k-tiles: one __syncthreads per k-chunk. Epilogue operands
// (g_xW, g_c, hcur) are prefetched into registers BEFORE the final compute
// so their memory latency hides under the last k-chunk's FFMA2 work.
// ---------------------------------------------------------------------------
__global__ __launch_bounds__(256) void lstm_step(const float* __restrict__ U,
                                                 const int* __restrict__ batch_sizes,
                                                 const float* __restrict__ tau_p,
                                                 float* __restrict__ out,
                                                 int t)
{
    __shared__ __align__(16) float As2[2][KC][130];  // duplicated A, stride 130
    __shared__ __align__(16) float Bs[2][KC][68];
    __shared__ __align__(16) float gs[64][68];  // raw gate preactivations (w/o xW)
    __shared__ float hf[64][2];    // final h ch0/1 (blocks with ny==0 only)

    const int tid = threadIdx.x;
    const int tx = tid & 15, ty = tid >> 4;
    const int m0  = blockIdx.x * 64;
    const int hc0 = blockIdx.y * 16;
    const int cur = t & 1;
    const float* __restrict__ hcur = g_h2[cur];
    float* __restrict__ hnext = g_h2[cur ^ 1];

    // Hoisted scalar loads: latency hidden under the GEMM mainloop.
    const int bs = batch_sizes[t];
    const float tau = *tau_p;

    const int am = tid >> 2, ak4 = (tid & 3) * 4;                        // A loader
    const int bk = tid >> 4, bq = (tid >> 2) & 3, bh4 = (tid & 3) * 4;   // B loader

    unsigned long long acc[4][2] = {};   // packed fp32x2 accumulators (4 rows x 2 col-pairs)

    // --- tile 0 load + store ---
    float4 av = *(const float4*)&hcur[(m0 + am) * HN + ak4];
    float4 bv = *(const float4*)&U[(size_t)bk * G4 + bq * 512 + hc0 + bh4];

    {
        *(float2*)&As2[0][ak4 + 0][2 * am] = make_float2(av.x, av.x);
        *(float2*)&As2[0][ak4 + 1][2 * am] = make_float2(av.y, av.y);
        *(float2*)&As2[0][ak4 + 2][2 * am] = make_float2(av.z, av.z);
        *(float2*)&As2[0][ak4 + 3][2 * am] = make_float2(av.w, av.w);
        *(float4*)&Bs[0][bk][bq * 16 + bh4] = bv;
    }
    __syncthreads();

    auto compute = [&](int pp) {
#pragma unroll
        for (int kk = 0; kk < KC; kk++) {
            ulonglong2 b01 = *(const ulonglong2*)&Bs[pp][kk][tx * 4];
            unsigned long long a0 = *(const unsigned long long*)&As2[pp][kk][2 * (ty * 4 + 0)];
            unsigned long long a1 = *(const unsigned long long*)&As2[pp][kk][2 * (ty * 4 + 1)];
            unsigned long long a2 = *(const unsigned long long*)&As2[pp][kk][2 * (ty * 4 + 2)];
            unsigned long long a3 = *(const unsigned long long*)&As2[pp][kk][2 * (ty * 4 + 3)];
            FFMA2(acc[0][0], a0, b01.x); FFMA2(acc[0][1], a0, b01.y);
            FFMA2(acc[1][0], a1, b01.x); FFMA2(acc[1][1], a1, b01.y);
            FFMA2(acc[2][0], a2, b01.x); FFMA2(acc[2][1], a2, b01.y);
            FFMA2(acc[3][0], a3, b01.x); FFMA2(acc[3][1], a3, b01.y);
        }
    };

    int p = 0;
    for (int kc = KC; kc < HN; kc += KC) {
        // prefetch next k-tile from global
        av = *(const float4*)&hcur[(m0 + am) * HN + kc + ak4];
        bv = *(const float4*)&U[(size_t)(kc + bk) * G4 + bq * 512 + hc0 + bh4];

        compute(p);

        int q = p ^ 1;
        *(float2*)&As2[q][ak4 + 0][2 * am] = make_float2(av.x, av.x);
        *(float2*)&As2[q][ak4 + 1][2 * am] = make_float2(av.y, av.y);
        *(float2*)&As2[q][ak4 + 2][2 * am] = make_float2(av.z, av.z);
        *(float2*)&As2[q][ak4 + 3][2 * am] = make_float2(av.w, av.w);
        *(float4*)&Bs[q][bk][bq * 16 + bh4] = bv;
        __syncthreads();
        p = q;
    }

    // Prefetch epilogue operands into registers BEFORE the final compute:
    // all are safe to read here (g_xW / hcur read-only this step; g_c[b,hidx]
    // is read+written by exactly this thread). 24 independent LDGs issued
    // with the last k-chunk's FFMA2 work covering their latency.
    float xwi[4], xwf[4], xwg[4], xwo[4], coldp[4], holdp[4];
#pragma unroll
    for (int r = 0; r < 4; r++) {
        int e = tid + 256 * r;
        int row = e >> 4, hh = e & 15;
        int b = m0 + row;
        int hidx = hc0 + hh;
        size_t xb = (size_t)b * G4;
        xwi[r]   = g_xW[xb + 0 * 512 + hidx];
        xwf[r]   = g_xW[xb + 1 * 512 + hidx];
        xwg[r]   = g_xW[xb + 2 * 512 + hidx];
        xwo[r]   = g_xW[xb + 3 * 512 + hidx];
        coldp[r] = g_c[b * HN + hidx];
        holdp[r] = hcur[b * HN + hidx];
    }

    compute(p);

    // Exchange: store packed fp32x2 accumulators directly (STS.64, no unpack MOVs)
    // so each element (row, hh) can gather i,f,g,o after the barrier.
    // gs row stride = 68 floats = 272 B (16B-aligned base); col = tx*4 + 2*jp is
    // 2-float aligned -> 8B-aligned STS.64.
#pragma unroll
    for (int i = 0; i < 4; i++) {
        int row = ty * 4 + i;
#pragma unroll
        for (int jp = 0; jp < 2; jp++) {
            *(unsigned long long*)&gs[row][tx * 4 + 2 * jp] = acc[i][jp];
        }
    }
    __syncthreads();

#pragma unroll
    for (int r = 0; r < 4; r++) {
        int e = tid + 256 * r;          // 0..1023 : 64 rows x 16 hidden cols
        int row = e >> 4, hh = e & 15;
        int b = m0 + row;
        int hidx = hc0 + hh;

        float iv = gs[row][hh]      + xwi[r];
        float fv = gs[row][16 + hh] + xwf[r];
        float gv = gs[row][32 + hh] + xwg[r];
        float ov = gs[row][48 + hh] + xwo[r];

        float cn = sigm(fv) * coldp[r] + sigm(iv) * tanhf(gv);
        float hn = sigm(ov) * tanhf(cn);

        bool msk = b < bs;
        float hfin = msk ? hn : holdp[r];

        if (msk) g_c[b * HN + hidx] = cn;
        out[(size_t)t * (BN * HN) + (size_t)b * HN + hidx] = msk ? hn : 0.0f;

        if (blockIdx.y == 0 && hh < 2) {
            hf[row][hh] = hfin;          // deferred: xcorr applied below
        } else {
            hnext[b * HN + hidx] = hfin;
        }
    }

    if (blockIdx.y == 0) {
        __syncthreads();                 // block-uniform branch: safe
        if (tid < 64) {
            int b = m0 + tid;
            // Fold next step's xcorr drift (reference applies it at step start,
            // t != 0, to ALL rows). Skip after the final step so returned h matches.
            float taue = (t == TN - 1) ? 0.0f : tau;
            float h0v = hf[tid][0], h1v = hf[tid][1];
            hnext[b * HN + 0] = h0v + taue * (1.5f * h0v + h1v * (1.0f / 1.5f));
            hnext[b * HN + 1] = h1v + taue * (-1.5f * h0v);
        }
    }
}

// ---------------------------------------------------------------------------
// Inputs (metadata order): rnn_input_data, batch_sizes, h0, c0, tau, W_w, W_b, U_w
// Output: concat( outputs[T,B,H], h[1,B,H], c[1,B,H] )  as float32
// ---------------------------------------------------------------------------
extern "C" void kernel_launch(void* const* d_in, const int* in_sizes, int n_in,
                              void* d_out, int out_size)
{
    (void)in_sizes; (void)n_in; (void)out_size;

    const float* x_in = (const float*)d_in[0];   // rnn_input_data (B*T, I); only first B rows used
    const int*   bsz  = (const int*)d_in[1];     // batch_sizes (T,)
    const float* h0   = (const float*)d_in[2];   // (1,B,H)
    const float* c0   = (const float*)d_in[3];   // (1,B,H)
    const float* tau  = (const float*)d_in[4];   // scalar
    const float* Ww   = (const float*)d_in[5];   // (I, 4H)
    const float* Wb   = (const float*)d_in[6];   // (4H,)
    const float* Uw   = (const float*)d_in[7];   // (H, 4H)
    float* out = (float*)d_out;

    void *hAddr = nullptr, *cAddr = nullptr;
    cudaGetSymbolAddress(&hAddr, g_h2);
    cudaGetSymbolAddress(&cAddr, g_c);

    // Init state: h -> ping buffer 0 (t=0 reads buf[t&1]=0), c in place.
    cudaMemcpyAsync(hAddr, h0, (size_t)BN * HN * sizeof(float),
                    cudaMemcpyDeviceToDevice, 0);
    cudaMemcpyAsync(cAddr, c0, (size_t)BN * HN * sizeof(float),
                    cudaMemcpyDeviceToDevice, 0);

    dim3 grid(4, 32);
    xw_gemm<<<grid, 256>>>(x_in, Ww, Wb);

    for (int t = 0; t < TN; t++)
        lstm_step<<<grid, 256>>>(Uw, bsz, tau, out, t);

    // Final h lives in buffer (TN & 1) = 0, i.e. the base of g_h2.
    cudaMemcpyAsync(out + (size_t)TN * BN * HN, hAddr,
                    (size_t)BN * HN * sizeof(float), cudaMemcpyDeviceToDevice, 0);
    cudaMemcpyAsync(out + (size_t)TN * BN * HN + (size_t)BN * HN, cAddr,
                    (size_t)BN * HN * sizeof(float), cudaMemcpyDeviceToDevice, 0);
}